// round 15
// baseline (speedup 1.0000x reference)
#include <cuda_runtime.h>
#include <cuda_fp16.h>
#include <cstdint>

#define N_NODES 50000
#define N_EDGES 800000
#define D 128
#define N_LAYERS 3
#define N_GRAPHS 512
#define NROWS 50176                     // padded to 392*128 (device globals zero-init)
#define ND (N_NODES * D)
#define NDP (NROWS * D)

#define SCAN_BLK 512
#define SCAN_NBLK ((N_NODES + SCAN_BLK - 1) / SCAN_BLK)   // 98

// fp16 B fragments: 8 ksteps x 16 nt x 32 lanes x 8 halves (bh0,bh1,bl0,bl1)
#define KSTEPS (D / 16)                       // 8
#define FRAGH_PER_LAYER (KSTEPS * 16 * 32 * 8)   // 32768 halves = 64KB

// ---------------- scratch (device globals; no allocation allowed) ----------------
__device__ float  g_h[NDP];                 // post-GEMM features (fp32), padded
__device__ uint4  g_xp[NROWS * 32];         // packed A: per row 32 chunks of 16B
                                            // chunk(row, lane): lane=ks*4+t ->
                                            // [hi(2t,2t+1), hi(2t+8,2t+9), lo.., lo..]
__device__ float  g_x[ND];                  // final layer output (pool input)
__device__ __half g_wfh[N_LAYERS * FRAGH_PER_LAYER];  // W split-fp16 fragments
__device__ float  g_dis[N_NODES];
__device__ int    g_deg[N_NODES];
__device__ int    g_cur[N_NODES];
__device__ int    g_off[N_NODES + 1];
__device__ int    g_bsum[SCAN_NBLK];
__device__ float2 g_em[N_EDGES];            // (src as int bits, norm)
__device__ float  g_gsum[N_GRAPHS];
__device__ int    g_gcnt[N_GRAPHS];

#define MMA_F16(c, a0, a1, a2, a3, b0, b1) \
    asm volatile("mma.sync.aligned.m16n8k16.row.col.f32.f16.f16.f32 " \
        "{%0,%1,%2,%3}, {%4,%5,%6,%7}, {%8,%9}, {%0,%1,%2,%3};" \
        : "+f"(c[0]), "+f"(c[1]), "+f"(c[2]), "+f"(c[3]) \
        : "r"(a0), "r"(a1), "r"(a2), "r"(a3), "r"(b0), "r"(b1))

__device__ __forceinline__ uint4 pack_hi_lo(float4 o) {
    __half2 hh0 = __floats2half2_rn(o.x, o.y);
    __half2 hh1 = __floats2half2_rn(o.z, o.w);
    float2 r0 = __half22float2(hh0);
    float2 r1 = __half22float2(hh1);
    __half2 ll0 = __floats2half2_rn(o.x - r0.x, o.y - r0.y);
    __half2 ll1 = __floats2half2_rn(o.z - r1.x, o.w - r1.y);
    uint4 pk;
    pk.x = *(uint32_t*)&hh0; pk.y = *(uint32_t*)&hh1;
    pk.z = *(uint32_t*)&ll0; pk.w = *(uint32_t*)&ll1;
    return pk;
}

// ---------------- W -> split-fp16 fragments (B-fragment order, m16n8k16) ----------------
__global__ void wfrag_k(const float* __restrict__ Ws) {
    int i = blockIdx.x * blockDim.x + threadIdx.x;
    if (i >= N_LAYERS * D * D) return;
    int l = i / (D * D);
    int rem = i - l * (D * D);
    int o = rem / D;           // Ws[l][o][k]
    int k = rem - o * D;
    float v = Ws[i];
    __half hi = __float2half_rn(v);
    __half lo = __float2half_rn(v - __half2float(hi));
    int kstep = k >> 4, kin = k & 15;
    int tig = (kin & 7) >> 1;
    int hpos = kin & 1;
    int b01 = kin >> 3;        // 0 -> b0, 1 -> b1
    int nt = o >> 3, gg = o & 7;
    int lane = gg * 4 + tig;
    size_t base = ((((size_t)l * KSTEPS + kstep) * 16 + nt) * 32 + lane) * 8;
    g_wfh[base + b01 * 2 + hpos]     = hi;
    g_wfh[base + 4 + b01 * 2 + hpos] = lo;
}

// ---------------- layer-0 input -> packed A ----------------
__global__ void pack0_k(const float* __restrict__ X) {
    int i = blockIdx.x * blockDim.x + threadIdx.x;
    if (i >= N_NODES * 32) return;
    int row = i >> 5;
    int lane = i & 31;
    int f0 = 16 * (lane >> 2) + 2 * (lane & 3);
    const float* xr = X + (size_t)row * D;
    float2 p = *(const float2*)(xr + f0);
    float2 q = *(const float2*)(xr + f0 + 8);
    g_xp[(size_t)row * 32 + lane] = pack_hi_lo(make_float4(p.x, p.y, q.x, q.y));
}

// ---------------- zero ----------------
__global__ void zero_misc_k() {
    int i = blockIdx.x * blockDim.x + threadIdx.x;
    if (i < N_NODES) { g_deg[i] = 0; g_cur[i] = 0; }
    if (i < N_GRAPHS) { g_gsum[i] = 0.f; g_gcnt[i] = 0; }
}

// ---------------- degree histogram ----------------
__global__ void deg_k(const int* __restrict__ ei) {
    int e = blockIdx.x * blockDim.x + threadIdx.x;
    if (e >= N_EDGES) return;
    atomicAdd(&g_deg[ei[N_EDGES + e]], 1);
}

// ---------------- scan (also computes dis) ----------------
__global__ void scan1_k() {
    __shared__ int sm[SCAN_BLK];
    int tid = threadIdx.x;
    int gid = blockIdx.x * SCAN_BLK + tid;
    int v = 0;
    if (gid < N_NODES) {
        v = g_deg[gid];
        g_dis[gid] = rsqrtf((float)(v + 1));
    }
    sm[tid] = v;
    __syncthreads();
    #pragma unroll
    for (int o = 1; o < SCAN_BLK; o <<= 1) {
        int t = (tid >= o) ? sm[tid - o] : 0;
        __syncthreads();
        sm[tid] += t;
        __syncthreads();
    }
    if (gid < N_NODES) g_off[gid] = sm[tid] - v;
    if (tid == SCAN_BLK - 1) g_bsum[blockIdx.x] = sm[tid];
}
__global__ void scan2_k() {
    if (threadIdx.x == 0) {
        int run = 0;
        for (int i = 0; i < SCAN_NBLK; i++) {
            int t = g_bsum[i];
            g_bsum[i] = run;
            run += t;
        }
    }
}
__global__ void scan3_k() {
    int gid = blockIdx.x * blockDim.x + threadIdx.x;
    if (gid < N_NODES) g_off[gid] += g_bsum[gid / SCAN_BLK];
    if (gid == 0) g_off[N_NODES] = N_EDGES;
}

// ---------------- counting-sort placement ----------------
__global__ void place_k(const int* __restrict__ ei) {
    int e = blockIdx.x * blockDim.x + threadIdx.x;
    if (e >= N_EDGES) return;
    int r = ei[e];
    int c = ei[N_EDGES + e];
    int idx = g_off[c] + atomicAdd(&g_cur[c], 1);
    g_em[idx] = make_float2(__int_as_float(r), g_dis[r] * g_dis[c]);
}

// ---------------- tensor-core GEMM: H = X @ W^T via split-fp16 (3 mma, k=16) ----------
// 256 threads (8 warps). Block = 128 rows x 128 cols. Warp tile = 16 x 128 (16 nt).
// A: packed g_xp -> TWO LDG.128 per kstep per thread (8 L1 wf each, was 128 total).
// B: 1 LDG.128 per (kstep,nt), feeds 3 MMAs, L1-resident.
__global__ void __launch_bounds__(256, 2)
gemm_tc_k(const uint4* __restrict__ XP, const uint4* __restrict__ Fr,
          float* __restrict__ H) {
    int tid = threadIdx.x;
    int wid = tid >> 5;
    int lane = tid & 31;
    int g = lane >> 2, tig = lane & 3;
    int r1 = blockIdx.x * 128 + wid * 16 + g;
    int r2 = r1 + 8;

    const uint4* ap = XP + (size_t)r1 * 32 + tig;
    const uint4* aq = XP + (size_t)r2 * 32 + tig;

    float acc[16][4];
    #pragma unroll
    for (int nt = 0; nt < 16; nt++) {
        acc[nt][0] = 0.f; acc[nt][1] = 0.f; acc[nt][2] = 0.f; acc[nt][3] = 0.f;
    }

    #pragma unroll
    for (int kstep = 0; kstep < KSTEPS; kstep++) {
        uint4 v0 = ap[kstep * 4];          // row r1: (a0, a2, la0, la2)
        uint4 v1 = aq[kstep * 4];          // row r2: (a1, a3, la1, la3)

        const uint4* bp = Fr + (kstep * 16) * 32 + lane;

        #pragma unroll
        for (int nt = 0; nt < 16; nt++) {
            uint4 f = __ldg(bp + nt * 32);    // (bh0, bh1, bl0, bl1)
            MMA_F16(acc[nt], v0.x, v1.x, v0.y, v1.y, f.x, f.y);   // hi*hi
            MMA_F16(acc[nt], v0.x, v1.x, v0.y, v1.y, f.z, f.w);   // hi*lo
            MMA_F16(acc[nt], v0.z, v1.z, v0.w, v1.w, f.x, f.y);   // lo*hi
        }
    }

    // store (rows padded -> no guards)
    #pragma unroll
    for (int nt = 0; nt < 16; nt++) {
        int col = nt * 8 + tig * 2;
        *(float2*)(H + (size_t)r1 * D + col) = make_float2(acc[nt][0], acc[nt][1]);
        *(float2*)(H + (size_t)r2 * D + col) = make_float2(acc[nt][2], acc[nt][3]);
    }
}

// ---------------- fused gather + self-loop + bias + relu; emits packed A ----------
// warp per node; lane (ks=lane>>2, t=lane&3) owns features {16ks+2t, +1, +8, +9}
__global__ void gather_k(const float* __restrict__ bias, int write_f32) {
    int gt = blockIdx.x * blockDim.x + threadIdx.x;
    int c = gt >> 5;
    int lane = gt & 31;
    if (c >= N_NODES) return;
    int f0 = 16 * (lane >> 2) + 2 * (lane & 3);    // features f0,f0+1,f0+8,f0+9

    int s = g_off[c];
    int e = g_off[c + 1];
    float4 acc = make_float4(0.f, 0.f, 0.f, 0.f);

    int i = s;
    for (; i + 4 <= e; i += 4) {
        float2 m0 = g_em[i + 0];
        float2 m1 = g_em[i + 1];
        float2 m2 = g_em[i + 2];
        float2 m3 = g_em[i + 3];
        const float* h0 = g_h + (size_t)__float_as_int(m0.x) * D + f0;
        const float* h1 = g_h + (size_t)__float_as_int(m1.x) * D + f0;
        const float* h2 = g_h + (size_t)__float_as_int(m2.x) * D + f0;
        const float* h3 = g_h + (size_t)__float_as_int(m3.x) * D + f0;
        float2 p0 = *(const float2*)h0, q0 = *(const float2*)(h0 + 8);
        float2 p1 = *(const float2*)h1, q1 = *(const float2*)(h1 + 8);
        float2 p2 = *(const float2*)h2, q2 = *(const float2*)(h2 + 8);
        float2 p3 = *(const float2*)h3, q3 = *(const float2*)(h3 + 8);
        acc.x += m0.y * p0.x + m1.y * p1.x + m2.y * p2.x + m3.y * p3.x;
        acc.y += m0.y * p0.y + m1.y * p1.y + m2.y * p2.y + m3.y * p3.y;
        acc.z += m0.y * q0.x + m1.y * q1.x + m2.y * q2.x + m3.y * q3.x;
        acc.w += m0.y * q0.y + m1.y * q1.y + m2.y * q2.y + m3.y * q3.y;
    }
    for (; i < e; i++) {
        float2 m = g_em[i];
        const float* hp = g_h + (size_t)__float_as_int(m.x) * D + f0;
        float2 p = *(const float2*)hp, q = *(const float2*)(hp + 8);
        acc.x += m.y * p.x; acc.y += m.y * p.y;
        acc.z += m.y * q.x; acc.w += m.y * q.y;
    }

    float d = g_dis[c];
    float d2 = d * d;
    const float* hc = g_h + (size_t)c * D + f0;
    float2 hs = *(const float2*)hc, ht = *(const float2*)(hc + 8);
    float2 b0 = *(const float2*)(bias + f0);
    float2 b1 = *(const float2*)(bias + f0 + 8);
    float4 o;
    o.x = fmaxf(acc.x + d2 * hs.x + b0.x, 0.f);
    o.y = fmaxf(acc.y + d2 * hs.y + b0.y, 0.f);
    o.z = fmaxf(acc.z + d2 * ht.x + b1.x, 0.f);
    o.w = fmaxf(acc.w + d2 * ht.y + b1.y, 0.f);

    g_xp[(size_t)c * 32 + lane] = pack_hi_lo(o);   // coalesced 512B per warp
    if (write_f32) {
        *(float2*)(g_x + (size_t)c * D + f0)     = make_float2(o.x, o.y);
        *(float2*)(g_x + (size_t)c * D + f0 + 8) = make_float2(o.z, o.w);
    }
}

// ---------------- pooling ----------------
__global__ void pool_k(const int* __restrict__ batch, const float* __restrict__ lw) {
    int gt = blockIdx.x * blockDim.x + threadIdx.x;
    int node = gt >> 5;
    int lane = gt & 31;
    if (node >= N_NODES) return;
    float4 xv = ((const float4*)g_x)[node * 32 + lane];
    float4 wv = ((const float4*)lw)[lane];
    float s = xv.x * wv.x + xv.y * wv.y + xv.z * wv.z + xv.w * wv.w;
    #pragma unroll
    for (int o = 16; o > 0; o >>= 1) s += __shfl_xor_sync(0xFFFFFFFFu, s, o);
    if (lane == 0) {
        int g = batch[node];
        atomicAdd(&g_gsum[g], s);
        atomicAdd(&g_gcnt[g], 1);
    }
}

__global__ void final_k(const float* __restrict__ lb, float* __restrict__ out) {
    int g = blockIdx.x * blockDim.x + threadIdx.x;
    if (g >= N_GRAPHS) return;
    float c = fmaxf((float)g_gcnt[g], 1.0f);
    out[g] = g_gsum[g] / c + lb[0];
}

// ---------------- launcher ----------------
extern "C" void kernel_launch(void* const* d_in, const int* in_sizes, int n_in,
                              void* d_out, int out_size) {
    const float* x    = (const float*)d_in[0];
    const int*   ei   = (const int*)d_in[1];    // int32 (JAX x64 disabled)
    const int*   bat  = (const int*)d_in[2];
    const float* Ws   = (const float*)d_in[3];
    const float* bs   = (const float*)d_in[4];
    const float* lw   = (const float*)d_in[5];
    const float* lb   = (const float*)d_in[6];
    float*       out  = (float*)d_out;

    float *h_p;
    uint4 *xp_p;
    __half *wfh_p;
    cudaGetSymbolAddress((void**)&h_p,   g_h);
    cudaGetSymbolAddress((void**)&xp_p,  g_xp);
    cudaGetSymbolAddress((void**)&wfh_p, g_wfh);

    const int gemm_blocks = NROWS / 128;             // 392
    const int gather_blocks = (N_NODES * 32 + 255) / 256;

    // launches 1-3: gemm prerequisites (keeps gemm as launch #4 for ncu)
    wfrag_k<<<(N_LAYERS * D * D + 255) / 256, 256>>>(Ws);
    pack0_k<<<(N_NODES * 32 + 255) / 256, 256>>>(x);
    zero_misc_k<<<(N_NODES + 255) / 256, 256>>>();

    // launch 4: layer-0 GEMM (ncu capture target)
    gemm_tc_k<<<gemm_blocks, 256>>>(xp_p, (const uint4*)wfh_p, h_p);

    // edge preprocessing (independent of gemm0)
    deg_k<<<(N_EDGES + 255) / 256, 256>>>(ei);
    scan1_k<<<SCAN_NBLK, SCAN_BLK>>>();
    scan2_k<<<1, 32>>>();
    scan3_k<<<(N_NODES + 255) / 256, 256>>>();
    place_k<<<(N_EDGES + 255) / 256, 256>>>(ei);

    // layer 0 gather, then layers 1..2
    gather_k<<<gather_blocks, 256>>>(bs, 0);
    for (int l = 1; l < N_LAYERS; l++) {
        gemm_tc_k<<<gemm_blocks, 256>>>(
            xp_p, (const uint4*)(wfh_p + (size_t)l * FRAGH_PER_LAYER), h_p);
        gather_k<<<gather_blocks, 256>>>(bs + l * D, (l == N_LAYERS - 1) ? 1 : 0);
    }

    // pooling + output
    pool_k<<<(N_NODES * 32 + 255) / 256, 256>>>(bat, lw);
    final_k<<<(N_GRAPHS + 255) / 256, 256>>>(lb, out);
}

// round 17
// speedup vs baseline: 1.1627x; 1.1627x over previous
#include <cuda_runtime.h>
#include <cuda_fp16.h>
#include <cstdint>

#define N_NODES 50000
#define N_EDGES 800000
#define D 128
#define N_LAYERS 3
#define N_GRAPHS 512
#define NROWS 50176                     // padded to 392*128 (device globals zero-init)
#define ND (N_NODES * D)
#define NDP (NROWS * D)

#define SCAN_BLK 512
#define SCAN_NBLK ((N_NODES + SCAN_BLK - 1) / SCAN_BLK)   // 98

// fp16 B fragments: 8 ksteps x 16 nt x 32 lanes x 8 halves (bh0,bh1,bl0,bl1)
#define KSTEPS (D / 16)                       // 8
#define FRAGH_PER_LAYER (KSTEPS * 16 * 32 * 8)   // 32768 halves = 64KB

// ---------------- scratch (device globals; no allocation allowed) ----------------
__device__ float  g_h[NDP];                 // post-GEMM features (fp32), padded
__device__ uint2  g_xp[NROWS * 32];         // packed A (hi only): per row 32 x 8B
                                            // chunk(row, l): ks=l>>2, t=l&3 ->
                                            // [hi(16ks+2t, +1), hi(16ks+2t+8, +9)]
__device__ float  g_x[ND];                  // final layer output (pool input)
__device__ __half g_wfh[N_LAYERS * FRAGH_PER_LAYER];  // W split-fp16 fragments
__device__ float  g_dis[N_NODES];
__device__ int    g_deg[N_NODES];
__device__ int    g_cur[N_NODES];
__device__ int    g_off[N_NODES + 1];
__device__ int    g_bsum[SCAN_NBLK];
__device__ float2 g_em[N_EDGES];            // (src as int bits, norm)
__device__ float  g_gsum[N_GRAPHS];
__device__ int    g_gcnt[N_GRAPHS];

#define MMA_F16(c, a0, a1, a2, a3, b0, b1) \
    asm volatile("mma.sync.aligned.m16n8k16.row.col.f32.f16.f16.f32 " \
        "{%0,%1,%2,%3}, {%4,%5,%6,%7}, {%8,%9}, {%0,%1,%2,%3};" \
        : "+f"(c[0]), "+f"(c[1]), "+f"(c[2]), "+f"(c[3]) \
        : "r"(a0), "r"(a1), "r"(a2), "r"(a3), "r"(b0), "r"(b1))

// ---------------- W -> split-fp16 fragments (B-fragment order, m16n8k16) ----------------
__global__ void wfrag_k(const float* __restrict__ Ws) {
    int i = blockIdx.x * blockDim.x + threadIdx.x;
    if (i >= N_LAYERS * D * D) return;
    int l = i / (D * D);
    int rem = i - l * (D * D);
    int o = rem / D;           // Ws[l][o][k]
    int k = rem - o * D;
    float v = Ws[i];
    __half hi = __float2half_rn(v);
    __half lo = __float2half_rn(v - __half2float(hi));
    int kstep = k >> 4, kin = k & 15;
    int tig = (kin & 7) >> 1;
    int hpos = kin & 1;
    int b01 = kin >> 3;        // 0 -> b0, 1 -> b1
    int nt = o >> 3, gg = o & 7;
    int lane = gg * 4 + tig;
    size_t base = ((((size_t)l * KSTEPS + kstep) * 16 + nt) * 32 + lane) * 8;
    g_wfh[base + b01 * 2 + hpos]     = hi;
    g_wfh[base + 4 + b01 * 2 + hpos] = lo;
}

// ---------------- layer-0 input -> packed A (hi only) ----------------
__global__ void pack0_k(const float* __restrict__ X) {
    int i = blockIdx.x * blockDim.x + threadIdx.x;
    if (i >= N_NODES * 32) return;
    int row = i >> 5;
    int lane = i & 31;
    int f0 = 16 * (lane >> 2) + 2 * (lane & 3);
    const float* xr = X + (size_t)row * D;
    float2 p = *(const float2*)(xr + f0);
    float2 q = *(const float2*)(xr + f0 + 8);
    __half2 hA = __floats2half2_rn(p.x, p.y);
    __half2 hB = __floats2half2_rn(q.x, q.y);
    uint2 pk;
    pk.x = *(uint32_t*)&hA; pk.y = *(uint32_t*)&hB;
    g_xp[(size_t)row * 32 + lane] = pk;
}

// ---------------- zero ----------------
__global__ void zero_misc_k() {
    int i = blockIdx.x * blockDim.x + threadIdx.x;
    if (i < N_NODES) { g_deg[i] = 0; g_cur[i] = 0; }
    if (i < N_GRAPHS) { g_gsum[i] = 0.f; g_gcnt[i] = 0; }
}

// ---------------- degree histogram ----------------
__global__ void deg_k(const int* __restrict__ ei) {
    int e = blockIdx.x * blockDim.x + threadIdx.x;
    if (e >= N_EDGES) return;
    atomicAdd(&g_deg[ei[N_EDGES + e]], 1);
}

// ---------------- scan (also computes dis) ----------------
__global__ void scan1_k() {
    __shared__ int sm[SCAN_BLK];
    int tid = threadIdx.x;
    int gid = blockIdx.x * SCAN_BLK + tid;
    int v = 0;
    if (gid < N_NODES) {
        v = g_deg[gid];
        g_dis[gid] = rsqrtf((float)(v + 1));
    }
    sm[tid] = v;
    __syncthreads();
    #pragma unroll
    for (int o = 1; o < SCAN_BLK; o <<= 1) {
        int t = (tid >= o) ? sm[tid - o] : 0;
        __syncthreads();
        sm[tid] += t;
        __syncthreads();
    }
    if (gid < N_NODES) g_off[gid] = sm[tid] - v;
    if (tid == SCAN_BLK - 1) g_bsum[blockIdx.x] = sm[tid];
}
__global__ void scan2_k() {
    if (threadIdx.x == 0) {
        int run = 0;
        for (int i = 0; i < SCAN_NBLK; i++) {
            int t = g_bsum[i];
            g_bsum[i] = run;
            run += t;
        }
    }
}
__global__ void scan3_k() {
    int gid = blockIdx.x * blockDim.x + threadIdx.x;
    if (gid < N_NODES) g_off[gid] += g_bsum[gid / SCAN_BLK];
    if (gid == 0) g_off[N_NODES] = N_EDGES;
}

// ---------------- counting-sort placement ----------------
__global__ void place_k(const int* __restrict__ ei) {
    int e = blockIdx.x * blockDim.x + threadIdx.x;
    if (e >= N_EDGES) return;
    int r = ei[e];
    int c = ei[N_EDGES + e];
    int idx = g_off[c] + atomicAdd(&g_cur[c], 1);
    g_em[idx] = make_float2(__int_as_float(r), g_dis[r] * g_dis[c]);
}

// ---------------- tensor-core GEMM: H = X @ W^T, hi*hi + hi*Wlo (2 mma, k=16) ------
// 256 threads (8 warps). Block = 128 rows x 128 cols. Warp tile = 16 x 128 (16 nt).
// A: packed hi-only g_xp -> ONE LDG.64 per kstep per row-pointer.
// B: 1 LDG.128 per (kstep,nt), feeds 2 MMAs, L1-resident.
__global__ void __launch_bounds__(256, 2)
gemm_tc_k(const uint2* __restrict__ XP, const uint4* __restrict__ Fr,
          float* __restrict__ H) {
    int tid = threadIdx.x;
    int wid = tid >> 5;
    int lane = tid & 31;
    int g = lane >> 2, tig = lane & 3;
    int r1 = blockIdx.x * 128 + wid * 16 + g;
    int r2 = r1 + 8;

    const uint2* ap = XP + (size_t)r1 * 32 + tig;
    const uint2* aq = XP + (size_t)r2 * 32 + tig;

    float acc[16][4];
    #pragma unroll
    for (int nt = 0; nt < 16; nt++) {
        acc[nt][0] = 0.f; acc[nt][1] = 0.f; acc[nt][2] = 0.f; acc[nt][3] = 0.f;
    }

    #pragma unroll
    for (int kstep = 0; kstep < KSTEPS; kstep++) {
        uint2 v0 = ap[kstep * 4];          // row r1: (a0, a2) hi
        uint2 v1 = aq[kstep * 4];          // row r2: (a1, a3) hi

        const uint4* bp = Fr + (kstep * 16) * 32 + lane;

        #pragma unroll
        for (int nt = 0; nt < 16; nt++) {
            uint4 f = __ldg(bp + nt * 32);    // (bh0, bh1, bl0, bl1)
            MMA_F16(acc[nt], v0.x, v1.x, v0.y, v1.y, f.x, f.y);   // hi*hi
            MMA_F16(acc[nt], v0.x, v1.x, v0.y, v1.y, f.z, f.w);   // hi*Wlo
        }
    }

    // store (rows padded -> no guards)
    #pragma unroll
    for (int nt = 0; nt < 16; nt++) {
        int col = nt * 8 + tig * 2;
        *(float2*)(H + (size_t)r1 * D + col) = make_float2(acc[nt][0], acc[nt][1]);
        *(float2*)(H + (size_t)r2 * D + col) = make_float2(acc[nt][2], acc[nt][3]);
    }
}

// ---------------- fused gather + self-loop + bias + relu; emits packed A ----------
// lane accumulates contiguous features [4*lane, 4*lane+4) with float4 loads (R12
// pattern), then a 4-shuffle exchange builds the (ks,t)-ordered packed chunk.
__global__ void gather_k(const float* __restrict__ bias, int write_f32) {
    int gt = blockIdx.x * blockDim.x + threadIdx.x;
    int c = gt >> 5;
    int lane = gt & 31;
    if (c >= N_NODES) return;

    int s = g_off[c];
    int e = g_off[c + 1];
    float4 acc = make_float4(0.f, 0.f, 0.f, 0.f);

    int i = s;
    for (; i + 4 <= e; i += 4) {
        float2 m0 = g_em[i + 0];
        float2 m1 = g_em[i + 1];
        float2 m2 = g_em[i + 2];
        float2 m3 = g_em[i + 3];
        const float4 v0 = *(const float4*)(g_h + (size_t)__float_as_int(m0.x) * D + lane * 4);
        const float4 v1 = *(const float4*)(g_h + (size_t)__float_as_int(m1.x) * D + lane * 4);
        const float4 v2 = *(const float4*)(g_h + (size_t)__float_as_int(m2.x) * D + lane * 4);
        const float4 v3 = *(const float4*)(g_h + (size_t)__float_as_int(m3.x) * D + lane * 4);
        acc.x += m0.y * v0.x + m1.y * v1.x + m2.y * v2.x + m3.y * v3.x;
        acc.y += m0.y * v0.y + m1.y * v1.y + m2.y * v2.y + m3.y * v3.y;
        acc.z += m0.y * v0.z + m1.y * v1.z + m2.y * v2.z + m3.y * v3.z;
        acc.w += m0.y * v0.w + m1.y * v1.w + m2.y * v2.w + m3.y * v3.w;
    }
    for (; i < e; i++) {
        float2 m = g_em[i];
        const float4 v = *(const float4*)(g_h + (size_t)__float_as_int(m.x) * D + lane * 4);
        acc.x += m.y * v.x; acc.y += m.y * v.y; acc.z += m.y * v.z; acc.w += m.y * v.w;
    }

    float d = g_dis[c];
    float d2 = d * d;
    float4 h = *(const float4*)(g_h + (size_t)c * D + lane * 4);
    float4 b = ((const float4*)bias)[lane];
    float4 o;
    o.x = fmaxf(acc.x + d2 * h.x + b.x, 0.f);
    o.y = fmaxf(acc.y + d2 * h.y + b.y, 0.f);
    o.z = fmaxf(acc.z + d2 * h.z + b.z, 0.f);
    o.w = fmaxf(acc.w + d2 * h.w + b.w, 0.f);

    // shuffle-exchange: chunk for this lane l (ks=l>>2, t=l&3) takes feature pairs
    // (16ks+2t, +1) from lane 4ks+(t>>1) and (+8, +9) from lane 4ks+(t>>1)+2,
    // selecting pair (x,y) if t even else (z,w).
    unsigned long long u01 = ((unsigned long long)__float_as_uint(o.y) << 32) |
                             __float_as_uint(o.x);
    unsigned long long u23 = ((unsigned long long)__float_as_uint(o.w) << 32) |
                             __float_as_uint(o.z);
    int srcA = 4 * (lane >> 2) + ((lane & 3) >> 1);
    int sel = lane & 1;
    unsigned long long axy = __shfl_sync(0xFFFFFFFFu, u01, srcA);
    unsigned long long azw = __shfl_sync(0xFFFFFFFFu, u23, srcA);
    unsigned long long bxy = __shfl_sync(0xFFFFFFFFu, u01, srcA + 2);
    unsigned long long bzw = __shfl_sync(0xFFFFFFFFu, u23, srcA + 2);
    unsigned long long A = sel ? azw : axy;
    unsigned long long B = sel ? bzw : bxy;
    __half2 hA = __floats2half2_rn(__uint_as_float((uint32_t)A),
                                   __uint_as_float((uint32_t)(A >> 32)));
    __half2 hB = __floats2half2_rn(__uint_as_float((uint32_t)B),
                                   __uint_as_float((uint32_t)(B >> 32)));
    uint2 pk;
    pk.x = *(uint32_t*)&hA; pk.y = *(uint32_t*)&hB;
    g_xp[(size_t)c * 32 + lane] = pk;              // coalesced 256B per warp

    if (write_f32) *(float4*)(g_x + (size_t)c * D + lane * 4) = o;
}

// ---------------- pooling ----------------
__global__ void pool_k(const int* __restrict__ batch, const float* __restrict__ lw) {
    int gt = blockIdx.x * blockDim.x + threadIdx.x;
    int node = gt >> 5;
    int lane = gt & 31;
    if (node >= N_NODES) return;
    float4 xv = ((const float4*)g_x)[node * 32 + lane];
    float4 wv = ((const float4*)lw)[lane];
    float s = xv.x * wv.x + xv.y * wv.y + xv.z * wv.z + xv.w * wv.w;
    #pragma unroll
    for (int o = 16; o > 0; o >>= 1) s += __shfl_xor_sync(0xFFFFFFFFu, s, o);
    if (lane == 0) {
        int g = batch[node];
        atomicAdd(&g_gsum[g], s);
        atomicAdd(&g_gcnt[g], 1);
    }
}

__global__ void final_k(const float* __restrict__ lb, float* __restrict__ out) {
    int g = blockIdx.x * blockDim.x + threadIdx.x;
    if (g >= N_GRAPHS) return;
    float c = fmaxf((float)g_gcnt[g], 1.0f);
    out[g] = g_gsum[g] / c + lb[0];
}

// ---------------- launcher ----------------
extern "C" void kernel_launch(void* const* d_in, const int* in_sizes, int n_in,
                              void* d_out, int out_size) {
    const float* x    = (const float*)d_in[0];
    const int*   ei   = (const int*)d_in[1];    // int32 (JAX x64 disabled)
    const int*   bat  = (const int*)d_in[2];
    const float* Ws   = (const float*)d_in[3];
    const float* bs   = (const float*)d_in[4];
    const float* lw   = (const float*)d_in[5];
    const float* lb   = (const float*)d_in[6];
    float*       out  = (float*)d_out;

    float *h_p;
    uint2 *xp_p;
    __half *wfh_p;
    cudaGetSymbolAddress((void**)&h_p,   g_h);
    cudaGetSymbolAddress((void**)&xp_p,  g_xp);
    cudaGetSymbolAddress((void**)&wfh_p, g_wfh);

    const int gemm_blocks = NROWS / 128;             // 392
    const int gather_blocks = (N_NODES * 32 + 255) / 256;

    // launches 1-3: gemm prerequisites (keeps gemm as launch #4 for ncu)
    wfrag_k<<<(N_LAYERS * D * D + 255) / 256, 256>>>(Ws);
    pack0_k<<<(N_NODES * 32 + 255) / 256, 256>>>(x);
    zero_misc_k<<<(N_NODES + 255) / 256, 256>>>();

    // launch 4: layer-0 GEMM (ncu capture target)
    gemm_tc_k<<<gemm_blocks, 256>>>(xp_p, (const uint4*)wfh_p, h_p);

    // edge preprocessing (independent of gemm0)
    deg_k<<<(N_EDGES + 255) / 256, 256>>>(ei);
    scan1_k<<<SCAN_NBLK, SCAN_BLK>>>();
    scan2_k<<<1, 32>>>();
    scan3_k<<<(N_NODES + 255) / 256, 256>>>();
    place_k<<<(N_EDGES + 255) / 256, 256>>>(ei);

    // layer 0 gather, then layers 1..2
    gather_k<<<gather_blocks, 256>>>(bs, 0);
    for (int l = 1; l < N_LAYERS; l++) {
        gemm_tc_k<<<gemm_blocks, 256>>>(
            xp_p, (const uint4*)(wfh_p + (size_t)l * FRAGH_PER_LAYER), h_p);
        gather_k<<<gather_blocks, 256>>>(bs + l * D, (l == N_LAYERS - 1) ? 1 : 0);
    }

    // pooling + output
    pool_k<<<(N_NODES * 32 + 255) / 256, 256>>>(bat, lw);
    final_k<<<(N_GRAPHS + 255) / 256, 256>>>(lb, out);
}